// round 15
// baseline (speedup 1.0000x reference)
#include <cuda_runtime.h>
#include <cuda_bf16.h>

#define DFT  784
#define DP   800
#define PAD  64
#define KC   50
#define LF   6
#define STW  30
#define NCAND 4

#define K1   800            // jf plane (784 + pad)
#define N1   1600           // 50 k * 32-stat stride (P21, q_ns6, nsmu2, ld)
#define K2   1600           // xj plane (800) + xj^2 plane (800)
#define N2   448            // 50 k * 8-stat stride (q_s6, cross, s2), padded
#define BM   128
#define BN   64
#define BK   32
#define NB1  (N1 / BN)      // 25
#define NB2  (N2 / BN)      // 7
#define NSTAGE 3
#define BMAX 2048

typedef unsigned long long u64;

// Exact fp32 tables: c_i = sqrt(invD)*a_i, s = sqrt(invD), nsmu = -s*mu
__device__ __align__(16) float4 g_C0[KC * DP + PAD];
__device__ __align__(16) float4 g_C1[KC * DP + PAD];
__device__ float g_LD[KC * DP + PAD];
// GEMM operands / outputs
__device__ __align__(16) __nv_bfloat16 g_F1[BMAX * K1];
__device__ __align__(16) __nv_bfloat16 g_F2[BMAX * K2];
__device__ __align__(16) __nv_bfloat16 g_W1[K1 * N1];
__device__ __align__(16) __nv_bfloat16 g_W2[K2 * N2];
__device__ float g_Cout1[BMAX * N1];
__device__ float g_Cout2[BMAX * N2];

__device__ __forceinline__ constexpr int IJ(int i, int j) { return i * (i + 1) / 2 + j; }

__device__ __forceinline__ unsigned smem_u32(const void* p) {
    return (unsigned)__cvta_generic_to_shared(p);
}
#define CP_ASYNC16(dst, src) \
    asm volatile("cp.async.cg.shared.global [%0], [%1], 16;\n" :: "r"(dst), "l"(src))
#define CP_COMMIT() asm volatile("cp.async.commit_group;\n" ::)
#define CP_WAIT1()  asm volatile("cp.async.wait_group 1;\n" ::)

// ---------------- pack exact tables ----------------
__global__ void pack_tables(const float* __restrict__ A_fac,
                            const float* __restrict__ MU,
                            const float* __restrict__ log_D)
{
    int idx = blockIdx.x * blockDim.x + threadIdx.x;
    if (idx >= KC * DP + PAD) return;
    int k = idx / DP, d = idx - k * DP;
    if (k < KC && d < DFT) {
        int src = k * DFT + d;
        const float* a = A_fac + (size_t)src * LF;
        float ld = log_D[src];
        float s  = expf(-0.5f * ld);
        g_C0[idx] = make_float4(s*a[0], s*a[1], s*a[2], s*a[3]);
        g_C1[idx] = make_float4(s*a[4], s*a[5], s, -s * MU[src]);
        g_LD[idx] = ld;
    } else {
        g_C0[idx] = make_float4(0.f,0.f,0.f,0.f);
        g_C1[idx] = make_float4(0.f,0.f,0.f,0.f);
        g_LD[idx] = 0.f;
    }
}

// ---------------- build F1 (jf) and F2 (xj | xj^2) ----------------
__global__ void build_F(const float* __restrict__ X, const int* __restrict__ J, int B)
{
    int idx = blockIdx.x * blockDim.x + threadIdx.x;
    if (idx >= B * DP) return;
    int b = idx / DP, d = idx - b * DP;
    float jf = 0.f, xj = 0.f;
    if (d < DFT) {
        bool jo = (J[(size_t)b * DFT + d] == 1);
        jf = jo ? 1.0f : 0.0f;
        xj = jo ? X[(size_t)b * DFT + d] : 0.0f;
    }
    g_F1[(size_t)b * K1 + d]       = __float2bfloat16(jf);
    g_F2[(size_t)b * K2 + d]       = __float2bfloat16(xj);
    g_F2[(size_t)b * K2 + DP + d]  = __float2bfloat16(xj * xj);
}

// ---------------- build W1 + W2 (fused) ----------------
__global__ void build_W()
{
    int idx = blockIdx.x * blockDim.x + threadIdx.x;
    if (idx < K1 * N1) {
        int r = idx / N1, c = idx - r * N1;
        int k = c >> 5, st = c & 31;
        float v = 0.f;
        if (r < DFT && st < 29) {
            float4 v0 = g_C0[k * DP + r];
            float4 v1 = g_C1[k * DP + r];
            float cc[LF] = {v0.x, v0.y, v0.z, v0.w, v1.x, v1.y};
            float nsmu = v1.w;
            if (st < 21) {
                int i = 0, rem = st;
                while (rem > i) { rem -= (i + 1); i++; }
                v = cc[i] * cc[rem];
            } else if (st < 27) v = nsmu * cc[st - 21];
            else if (st == 27)  v = nsmu * nsmu;
            else                v = g_LD[k * DP + r];
        }
        g_W1[idx] = __float2bfloat16(v);
        return;
    }
    int idx2 = idx - K1 * N1;
    if (idx2 >= K2 * N2) return;
    int r = idx2 / N2, c = idx2 - r * N2;
    int k = c >> 3, st = c & 7;
    float v = 0.f;
    if (k < KC) {
        if (r < DFT) {                       // xj plane
            float4 v0 = g_C0[k * DP + r];
            float4 v1 = g_C1[k * DP + r];
            float cc[LF] = {v0.x, v0.y, v0.z, v0.w, v1.x, v1.y};
            if (st < 6)       v = v1.z * cc[st];          // s * c_i
            else if (st == 6) v = 2.0f * v1.z * v1.w;     // 2 s nsmu
        } else if (r >= DP && r < DP + DFT) {             // xj^2 plane
            int d = r - DP;
            float s = g_C1[k * DP + d].z;
            if (st == 7) v = s * s;
        }
    }
    g_W2[idx2] = __float2bfloat16(v);
}

// ---------------- fused bf16 GEMMs (one launch, branch on blockIdx.y) ----------------
__global__ __launch_bounds__(256, 2)
void gemm_fused()
{
    __shared__ __align__(16) __nv_bfloat16 As[NSTAGE][BM][40];
    __shared__ __align__(16) __nv_bfloat16 Bs[NSTAGE][BK][72];

    const int tid  = threadIdx.x;
    const int lane = tid & 31, warp = tid >> 5;
    const int wm = warp >> 1, wn = warp & 1;
    const int bm = blockIdx.x;

    const __nv_bfloat16 *A, *W;
    float* C;
    int kdim, ndim, nkt, bn;
    if (blockIdx.y < NB1) {
        A = g_F1; W = g_W1; C = g_Cout1;
        kdim = K1; ndim = N1; nkt = K1 / BK; bn = blockIdx.y;
    } else {
        A = g_F2; W = g_W2; C = g_Cout2;
        kdim = K2; ndim = N2; nkt = K2 / BK; bn = blockIdx.y - NB1;
    }

    const int ar = tid >> 2, ac = (tid & 3) * 8;
    const int br = tid >> 3, bc = (tid & 7) * 8;

    const __nv_bfloat16* gA = A + (size_t)(bm * BM + ar) * kdim + ac;
    const __nv_bfloat16* gB = W + (size_t)br * ndim + bn * BN + bc;

    float acc[2][4][4];
    #pragma unroll
    for (int mi = 0; mi < 2; mi++)
        #pragma unroll
        for (int ni = 0; ni < 4; ni++)
            #pragma unroll
            for (int u = 0; u < 4; u++) acc[mi][ni][u] = 0.f;

    #pragma unroll
    for (int s = 0; s < NSTAGE - 1; s++) {
        const __nv_bfloat16* pa = gA + (size_t)s * BK;
        CP_ASYNC16(smem_u32(&As[s][ar][ac]), pa);
        CP_ASYNC16(smem_u32(&As[s][ar + 64][ac]), pa + (size_t)64 * kdim);
        CP_ASYNC16(smem_u32(&Bs[s][br][bc]), gB + (size_t)s * BK * ndim);
        CP_COMMIT();
    }

    int buf = 0;
    for (int kt = 0; kt < nkt; kt++) {
        CP_WAIT1();
        __syncthreads();

        if (kt + NSTAGE - 1 < nkt) {
            int nb = buf + 2; if (nb >= NSTAGE) nb -= NSTAGE;
            const __nv_bfloat16* pa = gA + (size_t)(kt + 2) * BK;
            CP_ASYNC16(smem_u32(&As[nb][ar][ac]), pa);
            CP_ASYNC16(smem_u32(&As[nb][ar + 64][ac]), pa + (size_t)64 * kdim);
            CP_ASYNC16(smem_u32(&Bs[nb][br][bc]), gB + (size_t)(kt + 2) * BK * ndim);
        }
        CP_COMMIT();

        #pragma unroll
        for (int ks = 0; ks < 2; ks++) {
            unsigned a[2][4], b[2][4];
            #pragma unroll
            for (int mi = 0; mi < 2; mi++) {
                unsigned addr = smem_u32(&As[buf][wm*32 + mi*16 + (lane & 15)]
                                            [ks*16 + ((lane >> 4) << 3)]);
                asm volatile("ldmatrix.sync.aligned.m8n8.x4.shared.b16 {%0,%1,%2,%3}, [%4];"
                             : "=r"(a[mi][0]), "=r"(a[mi][1]), "=r"(a[mi][2]), "=r"(a[mi][3])
                             : "r"(addr));
            }
            #pragma unroll
            for (int nj = 0; nj < 2; nj++) {
                unsigned addr = smem_u32(&Bs[buf][ks*16 + (lane & 15)]
                                            [wn*32 + nj*16 + ((lane >> 4) << 3)]);
                asm volatile("ldmatrix.sync.aligned.m8n8.x4.trans.shared.b16 {%0,%1,%2,%3}, [%4];"
                             : "=r"(b[nj][0]), "=r"(b[nj][1]), "=r"(b[nj][2]), "=r"(b[nj][3])
                             : "r"(addr));
            }
            #pragma unroll
            for (int mi = 0; mi < 2; mi++)
                #pragma unroll
                for (int nj = 0; nj < 2; nj++) {
                    asm volatile(
                        "mma.sync.aligned.m16n8k16.row.col.f32.bf16.bf16.f32 "
                        "{%0,%1,%2,%3}, {%4,%5,%6,%7}, {%8,%9}, {%0,%1,%2,%3};"
                        : "+f"(acc[mi][nj*2][0]), "+f"(acc[mi][nj*2][1]),
                          "+f"(acc[mi][nj*2][2]), "+f"(acc[mi][nj*2][3])
                        : "r"(a[mi][0]), "r"(a[mi][1]), "r"(a[mi][2]), "r"(a[mi][3]),
                          "r"(b[nj][0]), "r"(b[nj][1]));
                    asm volatile(
                        "mma.sync.aligned.m16n8k16.row.col.f32.bf16.bf16.f32 "
                        "{%0,%1,%2,%3}, {%4,%5,%6,%7}, {%8,%9}, {%0,%1,%2,%3};"
                        : "+f"(acc[mi][nj*2+1][0]), "+f"(acc[mi][nj*2+1][1]),
                          "+f"(acc[mi][nj*2+1][2]), "+f"(acc[mi][nj*2+1][3])
                        : "r"(a[mi][0]), "r"(a[mi][1]), "r"(a[mi][2]), "r"(a[mi][3]),
                          "r"(b[nj][2]), "r"(b[nj][3]));
                }
        }
        __syncthreads();
        buf++; if (buf >= NSTAGE) buf = 0;
    }

    #pragma unroll
    for (int mi = 0; mi < 2; mi++)
        #pragma unroll
        for (int ni = 0; ni < 4; ni++) {
            int row = bm * BM + wm * 32 + mi * 16 + (lane >> 2);
            int col = bn * BN + wn * 32 + ni * 8 + (lane & 3) * 2;
            float* p = C + (size_t)row * ndim + col;
            p[0] = acc[mi][ni][0]; p[1] = acc[mi][ni][1];
            float* p2 = p + 8 * ndim;
            p2[0] = acc[mi][ni][2]; p2[1] = acc[mi][ni][3];
        }
}

// ---------------- small linalg helpers ----------------
__device__ __forceinline__ float chol6(float* S, float* inv)
{
    float prod = 1.f;
    #pragma unroll
    for (int j = 0; j < LF; j++) {
        float s = S[IJ(j, j)];
        #pragma unroll
        for (int m = 0; m < j; m++) s = fmaf(-S[IJ(j, m)], S[IJ(j, m)], s);
        prod *= s;
        float rs = rsqrtf(s);
        inv[j] = rs;
        S[IJ(j, j)] = s * rs;
        #pragma unroll
        for (int i = j + 1; i < LF; i++) {
            float t = S[IJ(i, j)];
            #pragma unroll
            for (int m = 0; m < j; m++) t = fmaf(-S[IJ(i, m)], S[IJ(j, m)], t);
            S[IJ(i, j)] = t * rs;
        }
    }
    return prod;
}

__device__ __forceinline__ float fwd6(const float* L, const float* inv, const float* q, float* y)
{
    float ysq = 0.f;
    #pragma unroll
    for (int i = 0; i < LF; i++) {
        float t = q[i];
        #pragma unroll
        for (int m = 0; m < i; m++) t = fmaf(-L[IJ(i, m)], y[m], t);
        y[i] = t * inv[i];
        ysq = fmaf(y[i], y[i], ysq);
    }
    return ysq;
}

// ---------------- fused select + exact rescore + epilogue (block per sample) ----------------
__global__ __launch_bounds__(128, 4)
void select_rescore_final(const float* __restrict__ X, const int* __restrict__ J,
                          const float* __restrict__ MU, const float* __restrict__ A_fac,
                          const float* __restrict__ log_D, const float* __restrict__ PI,
                          float* __restrict__ outPw, float* __restrict__ outM,
                          float* __restrict__ outA, float* __restrict__ outD)
{
    __shared__ float s_score[KC];
    __shared__ int   s_cand[NCAND];
    __shared__ float s_ex[NCAND][STW];
    __shared__ float s_mz[LF], s_Lz[21];
    __shared__ int   s_c;

    const int b    = blockIdx.x;
    const int tid  = threadIdx.x;
    const int lane = tid & 31;
    const int warp = tid >> 5;

    // --- Phase A: approx scores for all 50 components (threads 0..49) ---
    if (tid < KC) {
        const int k = tid;
        const float* s1 = g_Cout1 + (size_t)b * N1 + k * 32;
        const float* s2 = g_Cout2 + (size_t)b * N2 + k * 8;
        float P[21], q[LF];
        #pragma unroll
        for (int u = 0; u < 21; u++) P[u] = s1[u];
        #pragma unroll
        for (int i = 0; i < LF; i++) { P[IJ(i, i)] += 1.0f; q[i] = s1[21 + i] + s2[i]; }
        float quad = s1[27] + s2[6] + s2[7];
        float jld  = s1[28];
        float inv[LF];
        float prod = chol6(P, inv);
        float y[LF];
        float ysq = fwd6(P, inv, q, y);
        float s = PI[k] - 0.5f * (quad - ysq + __logf(prod) + jld);
        s_score[k] = (s == s) ? s : -1e30f;     // NaN guard
    }
    __syncthreads();

    // --- Phase B: top-NCAND (ascending k => first-max tie semantics) ---
    if (tid == 0) {
        float ts[NCAND]; int tk[NCAND];
        #pragma unroll
        for (int c = 0; c < NCAND; c++) { ts[c] = -1e30f; tk[c] = 0; }
        for (int k = 0; k < KC; k++) {
            float sc = s_score[k];
            if (sc > ts[NCAND - 1]) {
                int p = NCAND - 1;
                while (p > 0 && sc > ts[p - 1]) { ts[p] = ts[p-1]; tk[p] = tk[p-1]; p--; }
                ts[p] = sc; tk[p] = k;
            }
        }
        #pragma unroll
        for (int c = 0; c < NCAND; c++) s_cand[c] = tk[c];
    }
    __syncthreads();

    // --- Phase C: exact fp32 rescore, one warp per candidate ---
    {
        const int k = s_cand[warp];
        const float4* __restrict__ p0 = g_C0 + (size_t)k * DP;
        const float4* __restrict__ p1 = g_C1 + (size_t)k * DP;
        const float*  __restrict__ pl = g_LD + (size_t)k * DP;

        float a[29];
        #pragma unroll
        for (int u = 0; u < 29; u++) a[u] = 0.f;

        for (int d = lane; d < DFT; d += 32) {
            float4 v0 = p0[d], v1 = p1[d];
            float ldv = pl[d];
            bool  jo  = (J[(size_t)b * DFT + d] == 1);
            float jf  = jo ? 1.0f : 0.0f;
            float xj  = jo ? X[(size_t)b * DFT + d] : 0.0f;
            float c[LF] = {v0.x, v0.y, v0.z, v0.w, v1.x, v1.y};
            float e = fmaf(v1.w, jf, v1.z * xj);
            a[27] = fmaf(e, e, a[27]);
            a[28] = fmaf(jf, ldv, a[28]);
            #pragma unroll
            for (int i = 0; i < LF; i++) {
                a[21 + i] = fmaf(e, c[i], a[21 + i]);
                float jc = jf * c[i];
                #pragma unroll
                for (int j = 0; j <= i; j++)
                    a[IJ(i, j)] = fmaf(jc, c[j], a[IJ(i, j)]);
            }
        }
        #pragma unroll
        for (int u = 0; u < 29; u++) {
            float v = a[u];
            #pragma unroll
            for (int off = 16; off > 0; off >>= 1)
                v += __shfl_xor_sync(0xffffffffu, v, off);
            a[u] = v;
        }
        if (lane == 0) {
            float P[21], q[LF];
            #pragma unroll
            for (int u = 0; u < 21; u++) P[u] = a[u];
            #pragma unroll
            for (int i = 0; i < LF; i++) { P[IJ(i, i)] += 1.0f; q[i] = a[21 + i]; }
            float inv[LF];
            float prod = chol6(P, inv);
            float y[LF];
            float ysq = fwd6(P, inv, q, y);
            #pragma unroll
            for (int u = 0; u < 29; u++) s_ex[warp][u] = a[u];
            s_ex[warp][29] = PI[k] - 0.5f * (a[27] - ysq + __logf(prod) + a[28]);
        }
    }
    __syncthreads();

    // --- Phase D: exact winner + small linalg (thread 0) ---
    if (tid == 0) {
        int wc = 0; float best = -1e30f;
        #pragma unroll
        for (int w = 0; w < NCAND; w++)
            if (s_ex[w][29] > best) { best = s_ex[w][29]; wc = w; }
        s_c = s_cand[wc];

        float P[21], q[LF];
        #pragma unroll
        for (int u = 0; u < 21; u++) P[u] = s_ex[wc][u];
        #pragma unroll
        for (int i = 0; i < LF; i++) { P[IJ(i, i)] += 1.0f; q[i] = s_ex[wc][21 + i]; }

        float inv[LF];
        (void)chol6(P, inv);
        float y[LF];
        (void)fwd6(P, inv, q, y);
        float mz[LF];
        #pragma unroll
        for (int ii = LF - 1; ii >= 0; ii--) {
            float t = y[ii];
            #pragma unroll
            for (int m = ii + 1; m < LF; m++) t = fmaf(-P[IJ(m, ii)], mz[m], t);
            mz[ii] = t * inv[ii];
        }
        float Li[21];
        #pragma unroll
        for (int j = 0; j < LF; j++) {
            Li[IJ(j, j)] = inv[j];
            #pragma unroll
            for (int i = j + 1; i < LF; i++) {
                float t = 0.f;
                #pragma unroll
                for (int m = j; m < i; m++) t = fmaf(P[IJ(i, m)], Li[IJ(m, j)], t);
                Li[IJ(i, j)] = -inv[i] * t;
            }
        }
        float C[21];
        #pragma unroll
        for (int i = 0; i < LF; i++)
            #pragma unroll
            for (int j = 0; j <= i; j++) {
                float t = 0.f;
                #pragma unroll
                for (int m = i; m < LF; m++) t = fmaf(Li[IJ(m, i)], Li[IJ(m, j)], t);
                C[IJ(i, j)] = t;
            }
        float invz[LF];
        (void)chol6(C, invz);
        #pragma unroll
        for (int i = 0; i < LF; i++) s_mz[i] = mz[i];
        #pragma unroll
        for (int u = 0; u < 21; u++) s_Lz[u] = C[u];
        outPw[b] = 1.0f;
    }
    __syncthreads();

    // --- Phase E: stream outputs (exact original inputs) ---
    const int c = s_c;
    float mz[LF], Lz[21];
    #pragma unroll
    for (int i = 0; i < LF; i++) mz[i] = s_mz[i];
    #pragma unroll
    for (int u = 0; u < 21; u++) Lz[u] = s_Lz[u];
    const float* __restrict__ ac  = A_fac + (size_t)c * DFT * LF;
    const float* __restrict__ muc = MU    + (size_t)c * DFT;
    const float* __restrict__ ldc = log_D + (size_t)c * DFT;
    for (int d = tid; d < DFT; d += 128) {
        const float2* ar = reinterpret_cast<const float2*>(ac + (size_t)d * LF);
        float2 r0 = ar[0], r1 = ar[1], r2 = ar[2];
        float a[LF] = {r0.x, r0.y, r1.x, r1.y, r2.x, r2.y};
        float Mo = muc[d];
        #pragma unroll
        for (int i = 0; i < LF; i++) Mo = fmaf(a[i], mz[i], Mo);
        outM[(size_t)b * DFT + d] = Mo;
        float Ao[LF];
        #pragma unroll
        for (int j = 0; j < LF; j++) {
            float s = 0.f;
            #pragma unroll
            for (int i = j; i < LF; i++) s = fmaf(a[i], Lz[IJ(i, j)], s);
            Ao[j] = s;
        }
        float2* pA = reinterpret_cast<float2*>(outA + ((size_t)b * DFT + d) * LF);
        pA[0] = make_float2(Ao[0], Ao[1]);
        pA[1] = make_float2(Ao[2], Ao[3]);
        pA[2] = make_float2(Ao[4], Ao[5]);
        outD[(size_t)b * DFT + d] = expf(ldc[d]);
    }
}

extern "C" void kernel_launch(void* const* d_in, const int* in_sizes, int n_in,
                              void* d_out, int out_size)
{
    const float* X      = (const float*)d_in[0];
    const int*   J      = (const int*)  d_in[1];
    const float* MU     = (const float*)d_in[2];
    const float* A_fac  = (const float*)d_in[3];
    const float* log_D  = (const float*)d_in[4];
    const float* PI     = (const float*)d_in[5];
    float* out = (float*)d_out;

    const int B = in_sizes[0] / DFT;     // 2048
    float* outPw = out;
    float* outM  = out + B;
    float* outA  = outM + (size_t)B * DFT;
    float* outD  = outA + (size_t)B * DFT * LF;

    pack_tables<<<(KC * DP + PAD + 255) / 256, 256>>>(A_fac, MU, log_D);
    build_F<<<(B * DP + 255) / 256, 256>>>(X, J, B);
    build_W<<<(K1 * N1 + K2 * N2 + 255) / 256, 256>>>();
    dim3 gg(B / BM, NB1 + NB2);
    gemm_fused<<<gg, 256>>>();
    select_rescore_final<<<B, 128>>>(X, J, MU, A_fac, log_D, PI, outPw, outM, outA, outD);
}

// round 16
// speedup vs baseline: 1.0342x; 1.0342x over previous
#include <cuda_runtime.h>
#include <cuda_bf16.h>

#define DFT  784
#define DP   800
#define PAD  64
#define KC   50
#define LF   6
#define STW  30
#define NCAND 4

#define K1   800            // jf plane (784 + pad)
#define N1   1600           // 50 k * 32-stat stride (P21, q_ns6, nsmu2, ld)
#define K2   1600           // xj plane (800) + xj^2 plane (800)
#define N2   448            // 50 k * 8-stat stride (q_s6, cross, s2), padded
#define BM   128
#define BN   64
#define BK   32
#define NB1  (N1 / BN)      // 25
#define NB2  (N2 / BN)      // 7
#define NSTAGE 3
#define BMAX 2048

typedef unsigned long long u64;

// Exact fp32 tables: c_i = sqrt(invD)*a_i, s = sqrt(invD), nsmu = -s*mu
__device__ __align__(16) float4 g_C0[KC * DP + PAD];
__device__ __align__(16) float4 g_C1[KC * DP + PAD];
__device__ float g_LD[KC * DP + PAD];
// GEMM operands / outputs
__device__ __align__(16) __nv_bfloat16 g_F1[BMAX * K1];
__device__ __align__(16) __nv_bfloat16 g_F2[BMAX * K2];
__device__ __align__(16) __nv_bfloat16 g_W1[K1 * N1];
__device__ __align__(16) __nv_bfloat16 g_W2[K2 * N2];
__device__ float g_Cout1[BMAX * N1];
__device__ float g_Cout2[BMAX * N2];

__device__ __forceinline__ constexpr int IJ(int i, int j) { return i * (i + 1) / 2 + j; }

__device__ __forceinline__ unsigned smem_u32(const void* p) {
    return (unsigned)__cvta_generic_to_shared(p);
}
#define CP_ASYNC16(dst, src) \
    asm volatile("cp.async.cg.shared.global [%0], [%1], 16;\n" :: "r"(dst), "l"(src))
#define CP_COMMIT() asm volatile("cp.async.commit_group;\n" ::)
#define CP_WAIT1()  asm volatile("cp.async.wait_group 1;\n" ::)

// ---------------- pack exact tables ----------------
__global__ void pack_tables(const float* __restrict__ A_fac,
                            const float* __restrict__ MU,
                            const float* __restrict__ log_D)
{
    int idx = blockIdx.x * blockDim.x + threadIdx.x;
    if (idx >= KC * DP + PAD) return;
    int k = idx / DP, d = idx - k * DP;
    if (k < KC && d < DFT) {
        int src = k * DFT + d;
        const float* a = A_fac + (size_t)src * LF;
        float ld = log_D[src];
        float s  = expf(-0.5f * ld);
        g_C0[idx] = make_float4(s*a[0], s*a[1], s*a[2], s*a[3]);
        g_C1[idx] = make_float4(s*a[4], s*a[5], s, -s * MU[src]);
        g_LD[idx] = ld;
    } else {
        g_C0[idx] = make_float4(0.f,0.f,0.f,0.f);
        g_C1[idx] = make_float4(0.f,0.f,0.f,0.f);
        g_LD[idx] = 0.f;
    }
}

// ---------------- build F1/F2 + W1/W2 (fused, after pack_tables) ----------------
#define FW_F_TOTAL (BMAX * DP)
#define FW_W1_TOTAL (K1 * N1)
#define FW_W2_TOTAL (K2 * N2)

__global__ void build_FW(const float* __restrict__ X, const int* __restrict__ J, int B)
{
    int idx = blockIdx.x * blockDim.x + threadIdx.x;
    if (idx < B * DP) {
        int b = idx / DP, d = idx - b * DP;
        float jf = 0.f, xj = 0.f;
        if (d < DFT) {
            bool jo = (J[(size_t)b * DFT + d] == 1);
            jf = jo ? 1.0f : 0.0f;
            xj = jo ? X[(size_t)b * DFT + d] : 0.0f;
        }
        g_F1[(size_t)b * K1 + d]       = __float2bfloat16(jf);
        g_F2[(size_t)b * K2 + d]       = __float2bfloat16(xj);
        g_F2[(size_t)b * K2 + DP + d]  = __float2bfloat16(xj * xj);
        return;
    }
    int i1 = idx - B * DP;
    if (i1 < FW_W1_TOTAL) {
        int r = i1 / N1, c = i1 - r * N1;
        int k = c >> 5, st = c & 31;
        float v = 0.f;
        if (r < DFT && st < 29) {
            float4 v0 = g_C0[k * DP + r];
            float4 v1 = g_C1[k * DP + r];
            float cc[LF] = {v0.x, v0.y, v0.z, v0.w, v1.x, v1.y};
            float nsmu = v1.w;
            if (st < 21) {
                int i = 0, rem = st;
                while (rem > i) { rem -= (i + 1); i++; }
                v = cc[i] * cc[rem];
            } else if (st < 27) v = nsmu * cc[st - 21];
            else if (st == 27)  v = nsmu * nsmu;
            else                v = g_LD[k * DP + r];
        }
        g_W1[i1] = __float2bfloat16(v);
        return;
    }
    int i2 = i1 - FW_W1_TOTAL;
    if (i2 >= FW_W2_TOTAL) return;
    int r = i2 / N2, c = i2 - r * N2;
    int k = c >> 3, st = c & 7;
    float v = 0.f;
    if (k < KC) {
        if (r < DFT) {                       // xj plane
            float4 v0 = g_C0[k * DP + r];
            float4 v1 = g_C1[k * DP + r];
            float cc[LF] = {v0.x, v0.y, v0.z, v0.w, v1.x, v1.y};
            if (st < 6)       v = v1.z * cc[st];          // s * c_i
            else if (st == 6) v = 2.0f * v1.z * v1.w;     // 2 s nsmu
        } else if (r >= DP && r < DP + DFT) {             // xj^2 plane
            int d = r - DP;
            float s = g_C1[k * DP + d].z;
            if (st == 7) v = s * s;
        }
    }
    g_W2[i2] = __float2bfloat16(v);
}

// ---------------- fused bf16 GEMMs (one launch, branch on blockIdx.y) ----------------
__global__ __launch_bounds__(256, 2)
void gemm_fused()
{
    __shared__ __align__(16) __nv_bfloat16 As[NSTAGE][BM][40];
    __shared__ __align__(16) __nv_bfloat16 Bs[NSTAGE][BK][72];

    const int tid  = threadIdx.x;
    const int lane = tid & 31, warp = tid >> 5;
    const int wm = warp >> 1, wn = warp & 1;
    const int bm = blockIdx.x;

    const __nv_bfloat16 *A, *W;
    float* C;
    int kdim, ndim, nkt, bn;
    if (blockIdx.y < NB1) {
        A = g_F1; W = g_W1; C = g_Cout1;
        kdim = K1; ndim = N1; nkt = K1 / BK; bn = blockIdx.y;
    } else {
        A = g_F2; W = g_W2; C = g_Cout2;
        kdim = K2; ndim = N2; nkt = K2 / BK; bn = blockIdx.y - NB1;
    }

    const int ar = tid >> 2, ac = (tid & 3) * 8;
    const int br = tid >> 3, bc = (tid & 7) * 8;

    const __nv_bfloat16* gA = A + (size_t)(bm * BM + ar) * kdim + ac;
    const __nv_bfloat16* gB = W + (size_t)br * ndim + bn * BN + bc;

    float acc[2][4][4];
    #pragma unroll
    for (int mi = 0; mi < 2; mi++)
        #pragma unroll
        for (int ni = 0; ni < 4; ni++)
            #pragma unroll
            for (int u = 0; u < 4; u++) acc[mi][ni][u] = 0.f;

    #pragma unroll
    for (int s = 0; s < NSTAGE - 1; s++) {
        const __nv_bfloat16* pa = gA + (size_t)s * BK;
        CP_ASYNC16(smem_u32(&As[s][ar][ac]), pa);
        CP_ASYNC16(smem_u32(&As[s][ar + 64][ac]), pa + (size_t)64 * kdim);
        CP_ASYNC16(smem_u32(&Bs[s][br][bc]), gB + (size_t)s * BK * ndim);
        CP_COMMIT();
    }

    int buf = 0;
    for (int kt = 0; kt < nkt; kt++) {
        CP_WAIT1();
        __syncthreads();   // single barrier per stage: all warps done with kt-1's
                           // compute (which read buffer buf+2 mod 3) before the
                           // cp.async below overwrites it.

        if (kt + NSTAGE - 1 < nkt) {
            int nb = buf + 2; if (nb >= NSTAGE) nb -= NSTAGE;
            const __nv_bfloat16* pa = gA + (size_t)(kt + 2) * BK;
            CP_ASYNC16(smem_u32(&As[nb][ar][ac]), pa);
            CP_ASYNC16(smem_u32(&As[nb][ar + 64][ac]), pa + (size_t)64 * kdim);
            CP_ASYNC16(smem_u32(&Bs[nb][br][bc]), gB + (size_t)(kt + 2) * BK * ndim);
        }
        CP_COMMIT();

        #pragma unroll
        for (int ks = 0; ks < 2; ks++) {
            unsigned a[2][4], b[2][4];
            #pragma unroll
            for (int mi = 0; mi < 2; mi++) {
                unsigned addr = smem_u32(&As[buf][wm*32 + mi*16 + (lane & 15)]
                                            [ks*16 + ((lane >> 4) << 3)]);
                asm volatile("ldmatrix.sync.aligned.m8n8.x4.shared.b16 {%0,%1,%2,%3}, [%4];"
                             : "=r"(a[mi][0]), "=r"(a[mi][1]), "=r"(a[mi][2]), "=r"(a[mi][3])
                             : "r"(addr));
            }
            #pragma unroll
            for (int nj = 0; nj < 2; nj++) {
                unsigned addr = smem_u32(&Bs[buf][ks*16 + (lane & 15)]
                                            [wn*32 + nj*16 + ((lane >> 4) << 3)]);
                asm volatile("ldmatrix.sync.aligned.m8n8.x4.trans.shared.b16 {%0,%1,%2,%3}, [%4];"
                             : "=r"(b[nj][0]), "=r"(b[nj][1]), "=r"(b[nj][2]), "=r"(b[nj][3])
                             : "r"(addr));
            }
            #pragma unroll
            for (int mi = 0; mi < 2; mi++)
                #pragma unroll
                for (int nj = 0; nj < 2; nj++) {
                    asm volatile(
                        "mma.sync.aligned.m16n8k16.row.col.f32.bf16.bf16.f32 "
                        "{%0,%1,%2,%3}, {%4,%5,%6,%7}, {%8,%9}, {%0,%1,%2,%3};"
                        : "+f"(acc[mi][nj*2][0]), "+f"(acc[mi][nj*2][1]),
                          "+f"(acc[mi][nj*2][2]), "+f"(acc[mi][nj*2][3])
                        : "r"(a[mi][0]), "r"(a[mi][1]), "r"(a[mi][2]), "r"(a[mi][3]),
                          "r"(b[nj][0]), "r"(b[nj][1]));
                    asm volatile(
                        "mma.sync.aligned.m16n8k16.row.col.f32.bf16.bf16.f32 "
                        "{%0,%1,%2,%3}, {%4,%5,%6,%7}, {%8,%9}, {%0,%1,%2,%3};"
                        : "+f"(acc[mi][nj*2+1][0]), "+f"(acc[mi][nj*2+1][1]),
                          "+f"(acc[mi][nj*2+1][2]), "+f"(acc[mi][nj*2+1][3])
                        : "r"(a[mi][0]), "r"(a[mi][1]), "r"(a[mi][2]), "r"(a[mi][3]),
                          "r"(b[nj][2]), "r"(b[nj][3]));
                }
        }
        buf++; if (buf >= NSTAGE) buf = 0;
    }

    #pragma unroll
    for (int mi = 0; mi < 2; mi++)
        #pragma unroll
        for (int ni = 0; ni < 4; ni++) {
            int row = bm * BM + wm * 32 + mi * 16 + (lane >> 2);
            int col = bn * BN + wn * 32 + ni * 8 + (lane & 3) * 2;
            float* p = C + (size_t)row * ndim + col;
            p[0] = acc[mi][ni][0]; p[1] = acc[mi][ni][1];
            float* p2 = p + 8 * ndim;
            p2[0] = acc[mi][ni][2]; p2[1] = acc[mi][ni][3];
        }
}

// ---------------- small linalg helpers ----------------
__device__ __forceinline__ float chol6(float* S, float* inv)
{
    float prod = 1.f;
    #pragma unroll
    for (int j = 0; j < LF; j++) {
        float s = S[IJ(j, j)];
        #pragma unroll
        for (int m = 0; m < j; m++) s = fmaf(-S[IJ(j, m)], S[IJ(j, m)], s);
        prod *= s;
        float rs = rsqrtf(s);
        inv[j] = rs;
        S[IJ(j, j)] = s * rs;
        #pragma unroll
        for (int i = j + 1; i < LF; i++) {
            float t = S[IJ(i, j)];
            #pragma unroll
            for (int m = 0; m < j; m++) t = fmaf(-S[IJ(i, m)], S[IJ(j, m)], t);
            S[IJ(i, j)] = t * rs;
        }
    }
    return prod;
}

__device__ __forceinline__ float fwd6(const float* L, const float* inv, const float* q, float* y)
{
    float ysq = 0.f;
    #pragma unroll
    for (int i = 0; i < LF; i++) {
        float t = q[i];
        #pragma unroll
        for (int m = 0; m < i; m++) t = fmaf(-L[IJ(i, m)], y[m], t);
        y[i] = t * inv[i];
        ysq = fmaf(y[i], y[i], ysq);
    }
    return ysq;
}

// ---------------- fused select + exact rescore + epilogue (block per sample) ----------------
__global__ __launch_bounds__(128, 4)
void select_rescore_final(const float* __restrict__ X, const int* __restrict__ J,
                          const float* __restrict__ MU, const float* __restrict__ A_fac,
                          const float* __restrict__ log_D, const float* __restrict__ PI,
                          float* __restrict__ outPw, float* __restrict__ outM,
                          float* __restrict__ outA, float* __restrict__ outD)
{
    __shared__ float s_score[KC];
    __shared__ int   s_cand[NCAND];
    __shared__ float s_ex[NCAND][STW];
    __shared__ float s_mz[LF], s_Lz[21];
    __shared__ int   s_c;

    const int b    = blockIdx.x;
    const int tid  = threadIdx.x;
    const int lane = tid & 31;
    const int warp = tid >> 5;

    // --- Phase A: approx scores for all 50 components (threads 0..49) ---
    if (tid < KC) {
        const int k = tid;
        const float* s1 = g_Cout1 + (size_t)b * N1 + k * 32;
        const float* s2 = g_Cout2 + (size_t)b * N2 + k * 8;
        float P[21], q[LF];
        #pragma unroll
        for (int u = 0; u < 21; u++) P[u] = s1[u];
        #pragma unroll
        for (int i = 0; i < LF; i++) { P[IJ(i, i)] += 1.0f; q[i] = s1[21 + i] + s2[i]; }
        float quad = s1[27] + s2[6] + s2[7];
        float jld  = s1[28];
        float inv[LF];
        float prod = chol6(P, inv);
        float y[LF];
        float ysq = fwd6(P, inv, q, y);
        float s = PI[k] - 0.5f * (quad - ysq + __logf(prod) + jld);
        s_score[k] = (s == s) ? s : -1e30f;     // NaN guard
    }
    __syncthreads();

    // --- Phase B: top-NCAND (ascending k => first-max tie semantics) ---
    if (tid == 0) {
        float ts[NCAND]; int tk[NCAND];
        #pragma unroll
        for (int c = 0; c < NCAND; c++) { ts[c] = -1e30f; tk[c] = 0; }
        for (int k = 0; k < KC; k++) {
            float sc = s_score[k];
            if (sc > ts[NCAND - 1]) {
                int p = NCAND - 1;
                while (p > 0 && sc > ts[p - 1]) { ts[p] = ts[p-1]; tk[p] = tk[p-1]; p--; }
                ts[p] = sc; tk[p] = k;
            }
        }
        #pragma unroll
        for (int c = 0; c < NCAND; c++) s_cand[c] = tk[c];
    }
    __syncthreads();

    // --- Phase C: exact fp32 rescore, one warp per candidate ---
    {
        const int k = s_cand[warp];
        const float4* __restrict__ p0 = g_C0 + (size_t)k * DP;
        const float4* __restrict__ p1 = g_C1 + (size_t)k * DP;
        const float*  __restrict__ pl = g_LD + (size_t)k * DP;

        float a[29];
        #pragma unroll
        for (int u = 0; u < 29; u++) a[u] = 0.f;

        for (int d = lane; d < DFT; d += 32) {
            float4 v0 = p0[d], v1 = p1[d];
            float ldv = pl[d];
            bool  jo  = (J[(size_t)b * DFT + d] == 1);
            float jf  = jo ? 1.0f : 0.0f;
            float xj  = jo ? X[(size_t)b * DFT + d] : 0.0f;
            float c[LF] = {v0.x, v0.y, v0.z, v0.w, v1.x, v1.y};
            float e = fmaf(v1.w, jf, v1.z * xj);
            a[27] = fmaf(e, e, a[27]);
            a[28] = fmaf(jf, ldv, a[28]);
            #pragma unroll
            for (int i = 0; i < LF; i++) {
                a[21 + i] = fmaf(e, c[i], a[21 + i]);
                float jc = jf * c[i];
                #pragma unroll
                for (int j = 0; j <= i; j++)
                    a[IJ(i, j)] = fmaf(jc, c[j], a[IJ(i, j)]);
            }
        }
        #pragma unroll
        for (int u = 0; u < 29; u++) {
            float v = a[u];
            #pragma unroll
            for (int off = 16; off > 0; off >>= 1)
                v += __shfl_xor_sync(0xffffffffu, v, off);
            a[u] = v;
        }
        if (lane == 0) {
            float P[21], q[LF];
            #pragma unroll
            for (int u = 0; u < 21; u++) P[u] = a[u];
            #pragma unroll
            for (int i = 0; i < LF; i++) { P[IJ(i, i)] += 1.0f; q[i] = a[21 + i]; }
            float inv[LF];
            float prod = chol6(P, inv);
            float y[LF];
            float ysq = fwd6(P, inv, q, y);
            #pragma unroll
            for (int u = 0; u < 29; u++) s_ex[warp][u] = a[u];
            s_ex[warp][29] = PI[k] - 0.5f * (a[27] - ysq + __logf(prod) + a[28]);
        }
    }
    __syncthreads();

    // --- Phase D: exact winner + small linalg (thread 0) ---
    if (tid == 0) {
        int wc = 0; float best = -1e30f;
        #pragma unroll
        for (int w = 0; w < NCAND; w++)
            if (s_ex[w][29] > best) { best = s_ex[w][29]; wc = w; }
        s_c = s_cand[wc];

        float P[21], q[LF];
        #pragma unroll
        for (int u = 0; u < 21; u++) P[u] = s_ex[wc][u];
        #pragma unroll
        for (int i = 0; i < LF; i++) { P[IJ(i, i)] += 1.0f; q[i] = s_ex[wc][21 + i]; }

        float inv[LF];
        (void)chol6(P, inv);
        float y[LF];
        (void)fwd6(P, inv, q, y);
        float mz[LF];
        #pragma unroll
        for (int ii = LF - 1; ii >= 0; ii--) {
            float t = y[ii];
            #pragma unroll
            for (int m = ii + 1; m < LF; m++) t = fmaf(-P[IJ(m, ii)], mz[m], t);
            mz[ii] = t * inv[ii];
        }
        float Li[21];
        #pragma unroll
        for (int j = 0; j < LF; j++) {
            Li[IJ(j, j)] = inv[j];
            #pragma unroll
            for (int i = j + 1; i < LF; i++) {
                float t = 0.f;
                #pragma unroll
                for (int m = j; m < i; m++) t = fmaf(P[IJ(i, m)], Li[IJ(m, j)], t);
                Li[IJ(i, j)] = -inv[i] * t;
            }
        }
        float C[21];
        #pragma unroll
        for (int i = 0; i < LF; i++)
            #pragma unroll
            for (int j = 0; j <= i; j++) {
                float t = 0.f;
                #pragma unroll
                for (int m = i; m < LF; m++) t = fmaf(Li[IJ(m, i)], Li[IJ(m, j)], t);
                C[IJ(i, j)] = t;
            }
        float invz[LF];
        (void)chol6(C, invz);
        #pragma unroll
        for (int i = 0; i < LF; i++) s_mz[i] = mz[i];
        #pragma unroll
        for (int u = 0; u < 21; u++) s_Lz[u] = C[u];
        outPw[b] = 1.0f;
    }
    __syncthreads();

    // --- Phase E: stream outputs (exact original inputs) ---
    const int c = s_c;
    float mz[LF], Lz[21];
    #pragma unroll
    for (int i = 0; i < LF; i++) mz[i] = s_mz[i];
    #pragma unroll
    for (int u = 0; u < 21; u++) Lz[u] = s_Lz[u];
    const float* __restrict__ ac  = A_fac + (size_t)c * DFT * LF;
    const float* __restrict__ muc = MU    + (size_t)c * DFT;
    const float* __restrict__ ldc = log_D + (size_t)c * DFT;
    for (int d = tid; d < DFT; d += 128) {
        const float2* ar = reinterpret_cast<const float2*>(ac + (size_t)d * LF);
        float2 r0 = ar[0], r1 = ar[1], r2 = ar[2];
        float a[LF] = {r0.x, r0.y, r1.x, r1.y, r2.x, r2.y};
        float Mo = muc[d];
        #pragma unroll
        for (int i = 0; i < LF; i++) Mo = fmaf(a[i], mz[i], Mo);
        outM[(size_t)b * DFT + d] = Mo;
        float Ao[LF];
        #pragma unroll
        for (int j = 0; j < LF; j++) {
            float s = 0.f;
            #pragma unroll
            for (int i = j; i < LF; i++) s = fmaf(a[i], Lz[IJ(i, j)], s);
            Ao[j] = s;
        }
        float2* pA = reinterpret_cast<float2*>(outA + ((size_t)b * DFT + d) * LF);
        pA[0] = make_float2(Ao[0], Ao[1]);
        pA[1] = make_float2(Ao[2], Ao[3]);
        pA[2] = make_float2(Ao[4], Ao[5]);
        outD[(size_t)b * DFT + d] = expf(ldc[d]);
    }
}

extern "C" void kernel_launch(void* const* d_in, const int* in_sizes, int n_in,
                              void* d_out, int out_size)
{
    const float* X      = (const float*)d_in[0];
    const int*   J      = (const int*)  d_in[1];
    const float* MU     = (const float*)d_in[2];
    const float* A_fac  = (const float*)d_in[3];
    const float* log_D  = (const float*)d_in[4];
    const float* PI     = (const float*)d_in[5];
    float* out = (float*)d_out;

    const int B = in_sizes[0] / DFT;     // 2048
    float* outPw = out;
    float* outM  = out + B;
    float* outA  = outM + (size_t)B * DFT;
    float* outD  = outA + (size_t)B * DFT * LF;

    pack_tables<<<(KC * DP + PAD + 255) / 256, 256>>>(A_fac, MU, log_D);
    const int fw_total = B * DP + FW_W1_TOTAL + FW_W2_TOTAL;
    build_FW<<<(fw_total + 255) / 256, 256>>>(X, J, B);
    dim3 gg(B / BM, NB1 + NB2);
    gemm_fused<<<gg, 256>>>();
    select_rescore_final<<<B, 128>>>(X, J, MU, A_fac, log_D, PI, outPw, outM, outA, outD);
}